// round 14
// baseline (speedup 1.0000x reference)
#include <cuda_runtime.h>
#include <cuda_bf16.h>
#include <cstdint>

#define N_NODES 100000
#define HDIM    256
#define E_EDGES 3200000
#define LAYERS  4
#define SCAN_B  1024
#define NBLK    ((N_NODES + SCAN_B - 1) / SCAN_B)   // 98

// ---------------- scratch (device globals; no allocation allowed) ----------
__device__ int   d_is64;
__device__ int   d_cnt[N_NODES];
__device__ int   d_off[N_NODES + 1];
__device__ int   d_cur[N_NODES];
__device__ int   d_src_sorted[E_EDGES];
__device__ int   d_bsum[128];
__device__ float d_mean[(size_t)N_NODES * HDIM];
__device__ float d_bufA[(size_t)N_NODES * HDIM];
__device__ float d_bufB[(size_t)N_NODES * HDIM];

// ---------------- dtype detection + CSR construction -----------------------
__device__ __forceinline__ int load_idx(const void* ei, long long pos) {
    if (d_is64) return (int)((const long long*)ei)[pos];
    return ((const int*)ei)[pos];
}

__global__ void zero_detect_kernel(const void* __restrict__ ei) {
    int i = blockIdx.x * blockDim.x + threadIdx.x;
    if (i < N_NODES) d_cnt[i] = 0;
    if (blockIdx.x == 0 && threadIdx.x == 0) {
        const long long* p = (const long long*)ei;
        int ok64 = 1;
        for (int q = 0; q < 64; q++) {
            long long v = p[q];
            if (v < 0 || v >= N_NODES) { ok64 = 0; break; }
        }
        d_is64 = ok64;
    }
}

__global__ void hist_kernel(const void* __restrict__ ei) {
    int e = blockIdx.x * blockDim.x + threadIdx.x;
    if (e < E_EDGES) {
        int d = load_idx(ei, (long long)E_EDGES + e);
        atomicAdd(&d_cnt[d], 1);
    }
}

__global__ void scan_pass1() {
    __shared__ int sm[SCAN_B];
    int tid = threadIdx.x;
    int gid = blockIdx.x * SCAN_B + tid;
    int v = (gid < N_NODES) ? d_cnt[gid] : 0;
    sm[tid] = v;
    __syncthreads();
    for (int ofs = 1; ofs < SCAN_B; ofs <<= 1) {
        int t = (tid >= ofs) ? sm[tid - ofs] : 0;
        __syncthreads();
        sm[tid] += t;
        __syncthreads();
    }
    if (gid < N_NODES) d_off[gid] = sm[tid] - v;
    if (tid == SCAN_B - 1) d_bsum[blockIdx.x] = sm[tid];
}

__global__ void scan_pass2() {
    __shared__ int sm[128];
    int tid = threadIdx.x;
    int v = (tid < NBLK) ? d_bsum[tid] : 0;
    sm[tid] = v;
    __syncthreads();
    for (int ofs = 1; ofs < 128; ofs <<= 1) {
        int t = (tid >= ofs) ? sm[tid - ofs] : 0;
        __syncthreads();
        sm[tid] += t;
        __syncthreads();
    }
    if (tid < NBLK) d_bsum[tid] = sm[tid] - v;
}

__global__ void scan_pass3() {
    int gid = blockIdx.x * SCAN_B + threadIdx.x;
    if (gid < N_NODES) {
        int o = d_off[gid] + d_bsum[blockIdx.x];
        d_off[gid] = o;
        d_cur[gid] = o;
    }
    if (gid == 0) d_off[N_NODES] = E_EDGES;
}

__global__ void scatter_kernel(const void* __restrict__ ei) {
    int e = blockIdx.x * blockDim.x + threadIdx.x;
    if (e < E_EDGES) {
        int s = load_idx(ei, e);
        int d = load_idx(ei, (long long)E_EDGES + e);
        int pos = atomicAdd(&d_cur[d], 1);
        d_src_sorted[pos] = s;
    }
}

// ---------------- mean aggregation: float4 gathers, no staging --------------
__global__ __launch_bounds__(256) void agg_kernel(const float* __restrict__ hin) {
    __shared__ float4 red[256];
    const int i    = blockIdx.x;
    const int tid  = threadIdx.x;
    const int esub = tid >> 6;     // 0..3  edge slot
    const int c4   = tid & 63;     // 0..63 channel quad

    const int start = d_off[i];
    const int deg   = d_off[i + 1] - start;
    const int* __restrict__ idxp = d_src_sorted + start;

    float4 acc = make_float4(0.f, 0.f, 0.f, 0.f);
    int jj = esub;
    for (; jj + 12 < deg; jj += 16) {
        int s0 = idxp[jj], s1 = idxp[jj + 4], s2 = idxp[jj + 8], s3 = idxp[jj + 12];
        float4 v0 = *(const float4*)&hin[(size_t)s0 * HDIM + c4 * 4];
        float4 v1 = *(const float4*)&hin[(size_t)s1 * HDIM + c4 * 4];
        float4 v2 = *(const float4*)&hin[(size_t)s2 * HDIM + c4 * 4];
        float4 v3 = *(const float4*)&hin[(size_t)s3 * HDIM + c4 * 4];
        acc.x += v0.x; acc.y += v0.y; acc.z += v0.z; acc.w += v0.w;
        acc.x += v1.x; acc.y += v1.y; acc.z += v1.z; acc.w += v1.w;
        acc.x += v2.x; acc.y += v2.y; acc.z += v2.z; acc.w += v2.w;
        acc.x += v3.x; acc.y += v3.y; acc.z += v3.z; acc.w += v3.w;
    }
    for (; jj < deg; jj += 4) {
        float4 v = *(const float4*)&hin[(size_t)idxp[jj] * HDIM + c4 * 4];
        acc.x += v.x; acc.y += v.y; acc.z += v.z; acc.w += v.w;
    }

    red[tid] = acc;
    __syncthreads();
    if (tid < 64) {
        float4 a = red[tid], b = red[tid + 64], c = red[tid + 128], d = red[tid + 192];
        float inv = 1.0f / (float)max(deg, 1);
        float4 o;
        o.x = (a.x + b.x + c.x + d.x) * inv;
        o.y = (a.y + b.y + c.y + d.y) * inv;
        o.z = (a.z + b.z + c.z + d.z) * inv;
        o.w = (a.w + b.w + c.w + d.w) * inv;
        *(float4*)&d_mean[(size_t)i * HDIM + tid * 4] = o;
    }
}

// ---------------- tensor-core GEMM: C = mean@Wl^T + h@Wr^T + b (+ReLU) -----
// Split-bf16 hi/lo 3-product fp32 emulation, ldmatrix.x4 fragments,
// register-prefetched A tiles. GBM=256 (512 threads, 16 warps): halves the
// block count -> W L2-traffic halves; 4 warps/SMSP hides fill latency.
#define GBM   256
#define GBN   128
#define GBK   32
#define GSTR  40
#define TILEA (GBM * GSTR)          // 10240 halves
#define TILEB (GBN * GSTR)          // 5120 halves
#define GSMEM ((2 * TILEA + 2 * TILEB) * 2)  // 61440 bytes

__device__ __forceinline__ void mma16816(float c[4], const uint32_t a[4],
                                         uint32_t b0, uint32_t b1) {
    asm volatile(
        "mma.sync.aligned.m16n8k16.row.col.f32.bf16.bf16.f32 "
        "{%0,%1,%2,%3}, {%4,%5,%6,%7}, {%8,%9}, {%0,%1,%2,%3};"
        : "+f"(c[0]), "+f"(c[1]), "+f"(c[2]), "+f"(c[3])
        : "r"(a[0]), "r"(a[1]), "r"(a[2]), "r"(a[3]), "r"(b0), "r"(b1));
}

__device__ __forceinline__ void ldmx4(uint32_t r[4], const void* p) {
    uint32_t a = (uint32_t)__cvta_generic_to_shared(p);
    asm volatile("ldmatrix.sync.aligned.m8n8.x4.shared.b16 {%0,%1,%2,%3}, [%4];"
                 : "=r"(r[0]), "=r"(r[1]), "=r"(r[2]), "=r"(r[3]) : "r"(a));
}

__device__ __forceinline__ uint32_t pack_bf2(__nv_bfloat16 a, __nv_bfloat16 b) {
    uint16_t ua = *(uint16_t*)&a, ub = *(uint16_t*)&b;
    return (uint32_t)ua | ((uint32_t)ub << 16);
}

__device__ __forceinline__ void split_store(
    __nv_bfloat16* Sh, __nv_bfloat16* Sl, int row, int kq, float4 v)
{
    __nv_bfloat16 h0 = __float2bfloat16_rn(v.x);
    __nv_bfloat16 h1 = __float2bfloat16_rn(v.y);
    __nv_bfloat16 h2 = __float2bfloat16_rn(v.z);
    __nv_bfloat16 h3 = __float2bfloat16_rn(v.w);
    __nv_bfloat16 l0 = __float2bfloat16_rn(v.x - __bfloat162float(h0));
    __nv_bfloat16 l1 = __float2bfloat16_rn(v.y - __bfloat162float(h1));
    __nv_bfloat16 l2 = __float2bfloat16_rn(v.z - __bfloat162float(h2));
    __nv_bfloat16 l3 = __float2bfloat16_rn(v.w - __bfloat162float(h3));
    *(uint32_t*)&Sh[row * GSTR + kq]     = pack_bf2(h0, h1);
    *(uint32_t*)&Sh[row * GSTR + kq + 2] = pack_bf2(h2, h3);
    *(uint32_t*)&Sl[row * GSTR + kq]     = pack_bf2(l0, l1);
    *(uint32_t*)&Sl[row * GSTR + kq + 2] = pack_bf2(l2, l3);
}

__global__ __launch_bounds__(512, 1) void gemm_kernel(
    const float* __restrict__ Am,   // mean  [N_NODES, 256]
    const float* __restrict__ Ah,   // h_in  [N_NODES, 256]
    const float* __restrict__ Wl,   // [256, 256] row-major (o, k)
    const float* __restrict__ Wr,   // [256, 256]
    const float* __restrict__ bias, // [256]
    float* __restrict__ C,          // [N_NODES, 256]
    int do_relu)
{
    extern __shared__ __nv_bfloat16 smem[];
    __nv_bfloat16* As_h = smem;                    // [256][40]
    __nv_bfloat16* As_l = smem + TILEA;
    __nv_bfloat16* Bs_h = smem + 2 * TILEA;        // [128][40]
    __nv_bfloat16* Bs_l = smem + 2 * TILEA + TILEB;

    const int t    = threadIdx.x;
    const int warp = t >> 5;          // 0..15
    const int lane = t & 31;
    const int wm   = warp >> 1;       // 0..7 (m)
    const int wn   = warp & 1;        // 0..1 (n)
    const int grp  = lane >> 2;
    const int tig  = lane & 3;
    const int row0 = blockIdx.y * GBM;   // row blocks on y
    const int col0 = blockIdx.x * GBN;   // 2 column blocks adjacent

    const int arow = lane & 15;
    const int acolofs = (lane >> 4) * 8;
    const int brow = (lane & 7) + ((lane >> 4) << 3);
    const int bcolofs = ((lane >> 3) & 1) * 8;

    const int lrow = t >> 3;            // 0..63 base row
    const int lkq  = (t & 7) * 4;       // 0..28

    float acc[2][8][4];
#pragma unroll
    for (int i = 0; i < 2; i++)
#pragma unroll
        for (int j = 0; j < 8; j++)
#pragma unroll
            for (int c = 0; c < 4; c++) acc[i][j][c] = 0.0f;

    // ---- prefetch A tile for kt=0 (256 rows: 4 x 64) ----
    float4 va[4];
#pragma unroll
    for (int r = 0; r < 4; r++) {
        int row = lrow + r * 64;
        va[r] = make_float4(0.f, 0.f, 0.f, 0.f);
        if (row0 + row < N_NODES)
            va[r] = *(const float4*)&Am[(size_t)(row0 + row) * HDIM + lkq];
    }

    for (int kt = 0; kt < 512; kt += GBK) {
        const float* Wsrc = (kt < 256) ? Wl : Wr;
        const int kl = kt & 255;

        // 1) issue B loads (128 rows: 2 x 64), latency hidden by A split
        float4 vb[2];
#pragma unroll
        for (int r = 0; r < 2; r++) {
            int row = lrow + r * 64;
            vb[r] = *(const float4*)&Wsrc[(size_t)(col0 + row) * HDIM + kl + lkq];
        }
        // 2) split + store A
#pragma unroll
        for (int r = 0; r < 4; r++)
            split_store(As_h, As_l, lrow + r * 64, lkq, va[r]);
        // 3) split + store B
#pragma unroll
        for (int r = 0; r < 2; r++)
            split_store(Bs_h, Bs_l, lrow + r * 64, lkq, vb[r]);
        __syncthreads();

        // 4) prefetch next A tile — LDG latency overlaps the MMA section
        if (kt + GBK < 512) {
            const float* Asrc = (kt + GBK < 256) ? Am : Ah;
            const int kl2 = (kt + GBK) & 255;
#pragma unroll
            for (int r = 0; r < 4; r++) {
                int row = lrow + r * 64;
                va[r] = make_float4(0.f, 0.f, 0.f, 0.f);
                if (row0 + row < N_NODES)
                    va[r] = *(const float4*)&Asrc[(size_t)(row0 + row) * HDIM + kl2 + lkq];
            }
        }

        // 5) MMA section
#pragma unroll
        for (int ks = 0; ks < 2; ks++) {
            const int k0 = ks * 16;
            uint32_t ah[2][4], al[2][4];
#pragma unroll
            for (int i = 0; i < 2; i++) {
                int m = wm * 32 + i * 16;
                ldmx4(ah[i], &As_h[(m + arow) * GSTR + k0 + acolofs]);
                ldmx4(al[i], &As_l[(m + arow) * GSTR + k0 + acolofs]);
            }
#pragma unroll
            for (int jp = 0; jp < 4; jp++) {
                int n = wn * 64 + jp * 16;
                uint32_t bh[4], bl[4];
                ldmx4(bh, &Bs_h[(n + brow) * GSTR + k0 + bcolofs]);
                ldmx4(bl, &Bs_l[(n + brow) * GSTR + k0 + bcolofs]);
#pragma unroll
                for (int i = 0; i < 2; i++) {
                    mma16816(acc[i][2 * jp],     ah[i], bh[0], bh[1]);
                    mma16816(acc[i][2 * jp],     ah[i], bl[0], bl[1]);
                    mma16816(acc[i][2 * jp],     al[i], bh[0], bh[1]);
                    mma16816(acc[i][2 * jp + 1], ah[i], bh[2], bh[3]);
                    mma16816(acc[i][2 * jp + 1], ah[i], bl[2], bl[3]);
                    mma16816(acc[i][2 * jp + 1], al[i], bh[2], bh[3]);
                }
            }
        }
        __syncthreads();
    }

    // ---- epilogue: bias + optional relu ----
#pragma unroll
    for (int i = 0; i < 2; i++) {
#pragma unroll
        for (int j = 0; j < 8; j++) {
            int col = col0 + wn * 64 + j * 8 + tig * 2;
            float b0 = bias[col], b1 = bias[col + 1];
            int r0 = row0 + wm * 32 + i * 16 + grp;
            int r1 = r0 + 8;
            float v0 = acc[i][j][0] + b0, v1 = acc[i][j][1] + b1;
            float v2 = acc[i][j][2] + b0, v3 = acc[i][j][3] + b1;
            if (do_relu) {
                v0 = fmaxf(v0, 0.f); v1 = fmaxf(v1, 0.f);
                v2 = fmaxf(v2, 0.f); v3 = fmaxf(v3, 0.f);
            }
            if (r0 < N_NODES) { float2 p; p.x = v0; p.y = v1;
                *(float2*)&C[(size_t)r0 * HDIM + col] = p; }
            if (r1 < N_NODES) { float2 p; p.x = v2; p.y = v3;
                *(float2*)&C[(size_t)r1 * HDIM + col] = p; }
        }
    }
}

// ---------------- launch ----------------------------------------------------
extern "C" void kernel_launch(void* const* d_in, const int* in_sizes, int n_in,
                              void* d_out, int out_size) {
    const float* x    = (const float*)d_in[0];
    const void*  ei   = d_in[1];
    const float* Wl   = (const float*)d_in[2];
    const float* Wr   = (const float*)d_in[3];
    const float* bias = (const float*)d_in[4];
    float*       out  = (float*)d_out;

    void *pA, *pB, *pM;
    cudaGetSymbolAddress(&pA, d_bufA);
    cudaGetSymbolAddress(&pB, d_bufB);
    cudaGetSymbolAddress(&pM, d_mean);
    float* bufA = (float*)pA;
    float* bufB = (float*)pB;
    float* mean = (float*)pM;

    cudaFuncSetAttribute(gemm_kernel,
                         cudaFuncAttributeMaxDynamicSharedMemorySize, GSMEM);

    int nblocks = (N_NODES + 255) / 256;
    zero_detect_kernel<<<nblocks, 256>>>(ei);

    int eblocks = (E_EDGES + 255) / 256;
    hist_kernel<<<eblocks, 256>>>(ei);
    scan_pass1<<<NBLK, SCAN_B>>>();
    scan_pass2<<<1, 128>>>();
    scan_pass3<<<NBLK, SCAN_B>>>();
    scatter_kernel<<<eblocks, 256>>>(ei);

    dim3 ggrid(HDIM / GBN, (N_NODES + GBM - 1) / GBM);   // (2, 391)

    const float* hin = x;
    for (int l = 0; l < LAYERS; l++) {
        agg_kernel<<<N_NODES, 256>>>(hin);
        float* hout = (l == LAYERS - 1) ? out : ((l & 1) ? bufB : bufA);
        gemm_kernel<<<ggrid, 512, GSMEM>>>(mean, hin,
                                    Wl + (size_t)l * HDIM * HDIM,
                                    Wr + (size_t)l * HDIM * HDIM,
                                    bias + (size_t)l * HDIM,
                                    hout, (l < LAYERS - 1) ? 1 : 0);
        hin = hout;
    }
}

// round 15
// speedup vs baseline: 1.1118x; 1.1118x over previous
#include <cuda_runtime.h>
#include <cuda_bf16.h>
#include <cstdint>

#define N_NODES 100000
#define HDIM    256
#define E_EDGES 3200000
#define LAYERS  4
#define SCAN_B  1024
#define NBLK    ((N_NODES + SCAN_B - 1) / SCAN_B)   // 98

// ---------------- scratch (device globals; no allocation allowed) ----------
__device__ int   d_is64;
__device__ int   d_cnt[N_NODES];
__device__ int   d_off[N_NODES + 1];
__device__ int   d_cur[N_NODES];
__device__ int   d_src_sorted[E_EDGES];
__device__ int   d_bsum[128];
__device__ float d_mean[(size_t)N_NODES * HDIM];
__device__ float d_bufA[(size_t)N_NODES * HDIM];
__device__ float d_bufB[(size_t)N_NODES * HDIM];

// ---------------- dtype detection + CSR construction -----------------------
__global__ void zero_detect_kernel(const void* __restrict__ ei) {
    int i = blockIdx.x * blockDim.x + threadIdx.x;
    if (i < N_NODES) d_cnt[i] = 0;
    if (blockIdx.x == 0 && threadIdx.x == 0) {
        const long long* p = (const long long*)ei;
        int ok64 = 1;
        for (int q = 0; q < 64; q++) {
            long long v = p[q];
            if (v < 0 || v >= N_NODES) { ok64 = 0; break; }
        }
        d_is64 = ok64;
    }
}

// 2 edges per thread; paired vector index loads (E_EDGES is even).
__global__ void hist_kernel(const void* __restrict__ ei) {
    int e = (blockIdx.x * blockDim.x + threadIdx.x) * 2;
    if (e >= E_EDGES) return;
    int d0, d1;
    if (d_is64) {
        longlong2 v = *(const longlong2*)((const long long*)ei + E_EDGES + e);
        d0 = (int)v.x; d1 = (int)v.y;
    } else {
        int2 v = *(const int2*)((const int*)ei + E_EDGES + e);
        d0 = v.x; d1 = v.y;
    }
    atomicAdd(&d_cnt[d0], 1);
    atomicAdd(&d_cnt[d1], 1);
}

__global__ void scan_pass1() {
    __shared__ int sm[SCAN_B];
    int tid = threadIdx.x;
    int gid = blockIdx.x * SCAN_B + tid;
    int v = (gid < N_NODES) ? d_cnt[gid] : 0;
    sm[tid] = v;
    __syncthreads();
    for (int ofs = 1; ofs < SCAN_B; ofs <<= 1) {
        int t = (tid >= ofs) ? sm[tid - ofs] : 0;
        __syncthreads();
        sm[tid] += t;
        __syncthreads();
    }
    if (gid < N_NODES) d_off[gid] = sm[tid] - v;
    if (tid == SCAN_B - 1) d_bsum[blockIdx.x] = sm[tid];
}

__global__ void scan_pass2() {
    __shared__ int sm[128];
    int tid = threadIdx.x;
    int v = (tid < NBLK) ? d_bsum[tid] : 0;
    sm[tid] = v;
    __syncthreads();
    for (int ofs = 1; ofs < 128; ofs <<= 1) {
        int t = (tid >= ofs) ? sm[tid - ofs] : 0;
        __syncthreads();
        sm[tid] += t;
        __syncthreads();
    }
    if (tid < NBLK) d_bsum[tid] = sm[tid] - v;
}

__global__ void scan_pass3() {
    int gid = blockIdx.x * SCAN_B + threadIdx.x;
    if (gid < N_NODES) {
        int o = d_off[gid] + d_bsum[blockIdx.x];
        d_off[gid] = o;
        d_cur[gid] = o;
    }
    if (gid == 0) d_off[N_NODES] = E_EDGES;
}

__global__ void scatter_kernel(const void* __restrict__ ei) {
    int e = (blockIdx.x * blockDim.x + threadIdx.x) * 2;
    if (e >= E_EDGES) return;
    int s0, s1, d0, d1;
    if (d_is64) {
        longlong2 vs = *(const longlong2*)((const long long*)ei + e);
        longlong2 vd = *(const longlong2*)((const long long*)ei + E_EDGES + e);
        s0 = (int)vs.x; s1 = (int)vs.y;
        d0 = (int)vd.x; d1 = (int)vd.y;
    } else {
        int2 vs = *(const int2*)((const int*)ei + e);
        int2 vd = *(const int2*)((const int*)ei + E_EDGES + e);
        s0 = vs.x; s1 = vs.y;
        d0 = vd.x; d1 = vd.y;
    }
    int p0 = atomicAdd(&d_cur[d0], 1);
    d_src_sorted[p0] = s0;
    int p1 = atomicAdd(&d_cur[d1], 1);
    d_src_sorted[p1] = s1;
}

// ---------------- mean aggregation: float4 gathers, no staging --------------
// Block = one node. 256 threads = 4 edge-slots x 64 channel-quads.
__global__ __launch_bounds__(256) void agg_kernel(const float* __restrict__ hin) {
    __shared__ float4 red[256];
    const int i    = blockIdx.x;
    const int tid  = threadIdx.x;
    const int esub = tid >> 6;     // 0..3  edge slot
    const int c4   = tid & 63;     // 0..63 channel quad

    const int start = d_off[i];
    const int deg   = d_off[i + 1] - start;
    const int* __restrict__ idxp = d_src_sorted + start;

    float4 acc = make_float4(0.f, 0.f, 0.f, 0.f);
    int jj = esub;
    for (; jj + 12 < deg; jj += 16) {
        int s0 = idxp[jj], s1 = idxp[jj + 4], s2 = idxp[jj + 8], s3 = idxp[jj + 12];
        float4 v0 = *(const float4*)&hin[(size_t)s0 * HDIM + c4 * 4];
        float4 v1 = *(const float4*)&hin[(size_t)s1 * HDIM + c4 * 4];
        float4 v2 = *(const float4*)&hin[(size_t)s2 * HDIM + c4 * 4];
        float4 v3 = *(const float4*)&hin[(size_t)s3 * HDIM + c4 * 4];
        acc.x += v0.x; acc.y += v0.y; acc.z += v0.z; acc.w += v0.w;
        acc.x += v1.x; acc.y += v1.y; acc.z += v1.z; acc.w += v1.w;
        acc.x += v2.x; acc.y += v2.y; acc.z += v2.z; acc.w += v2.w;
        acc.x += v3.x; acc.y += v3.y; acc.z += v3.z; acc.w += v3.w;
    }
    for (; jj < deg; jj += 4) {
        float4 v = *(const float4*)&hin[(size_t)idxp[jj] * HDIM + c4 * 4];
        acc.x += v.x; acc.y += v.y; acc.z += v.z; acc.w += v.w;
    }

    red[tid] = acc;
    __syncthreads();
    if (tid < 64) {
        float4 a = red[tid], b = red[tid + 64], c = red[tid + 128], d = red[tid + 192];
        float inv = 1.0f / (float)max(deg, 1);
        float4 o;
        o.x = (a.x + b.x + c.x + d.x) * inv;
        o.y = (a.y + b.y + c.y + d.y) * inv;
        o.z = (a.z + b.z + c.z + d.z) * inv;
        o.w = (a.w + b.w + c.w + d.w) * inv;
        *(float4*)&d_mean[(size_t)i * HDIM + tid * 4] = o;
    }
}

// ---------------- tensor-core GEMM: C = mean@Wl^T + h@Wr^T + b (+ReLU) -----
// Split-bf16 hi/lo 3-product fp32 emulation, ldmatrix.x4 fragments,
// register-prefetched A tiles. (R12 configuration — local optimum.)
#define GBM  128
#define GBN  128
#define GBK  32
#define GSTR 40

__device__ __forceinline__ void mma16816(float c[4], const uint32_t a[4],
                                         uint32_t b0, uint32_t b1) {
    asm volatile(
        "mma.sync.aligned.m16n8k16.row.col.f32.bf16.bf16.f32 "
        "{%0,%1,%2,%3}, {%4,%5,%6,%7}, {%8,%9}, {%0,%1,%2,%3};"
        : "+f"(c[0]), "+f"(c[1]), "+f"(c[2]), "+f"(c[3])
        : "r"(a[0]), "r"(a[1]), "r"(a[2]), "r"(a[3]), "r"(b0), "r"(b1));
}

__device__ __forceinline__ void ldmx4(uint32_t r[4], const void* p) {
    uint32_t a = (uint32_t)__cvta_generic_to_shared(p);
    asm volatile("ldmatrix.sync.aligned.m8n8.x4.shared.b16 {%0,%1,%2,%3}, [%4];"
                 : "=r"(r[0]), "=r"(r[1]), "=r"(r[2]), "=r"(r[3]) : "r"(a));
}

__device__ __forceinline__ uint32_t pack_bf2(__nv_bfloat16 a, __nv_bfloat16 b) {
    uint16_t ua = *(uint16_t*)&a, ub = *(uint16_t*)&b;
    return (uint32_t)ua | ((uint32_t)ub << 16);
}

__device__ __forceinline__ void split_store(
    __nv_bfloat16 (*Sh)[GSTR], __nv_bfloat16 (*Sl)[GSTR],
    int row, int kq, float4 v)
{
    __nv_bfloat16 h0 = __float2bfloat16_rn(v.x);
    __nv_bfloat16 h1 = __float2bfloat16_rn(v.y);
    __nv_bfloat16 h2 = __float2bfloat16_rn(v.z);
    __nv_bfloat16 h3 = __float2bfloat16_rn(v.w);
    __nv_bfloat16 l0 = __float2bfloat16_rn(v.x - __bfloat162float(h0));
    __nv_bfloat16 l1 = __float2bfloat16_rn(v.y - __bfloat162float(h1));
    __nv_bfloat16 l2 = __float2bfloat16_rn(v.z - __bfloat162float(h2));
    __nv_bfloat16 l3 = __float2bfloat16_rn(v.w - __bfloat162float(h3));
    *(uint32_t*)&Sh[row][kq]     = pack_bf2(h0, h1);
    *(uint32_t*)&Sh[row][kq + 2] = pack_bf2(h2, h3);
    *(uint32_t*)&Sl[row][kq]     = pack_bf2(l0, l1);
    *(uint32_t*)&Sl[row][kq + 2] = pack_bf2(l2, l3);
}

__global__ __launch_bounds__(256, 2) void gemm_kernel(
    const float* __restrict__ Am,   // mean  [N_NODES, 256]
    const float* __restrict__ Ah,   // h_in  [N_NODES, 256]
    const float* __restrict__ Wl,   // [256, 256] row-major (o, k)
    const float* __restrict__ Wr,   // [256, 256]
    const float* __restrict__ bias, // [256]
    float* __restrict__ C,          // [N_NODES, 256]
    int do_relu)
{
    __shared__ __nv_bfloat16 As_h[GBM][GSTR];
    __shared__ __nv_bfloat16 As_l[GBM][GSTR];
    __shared__ __nv_bfloat16 Bs_h[GBN][GSTR];
    __shared__ __nv_bfloat16 Bs_l[GBN][GSTR];

    const int t    = threadIdx.x;
    const int warp = t >> 5;
    const int lane = t & 31;
    const int wm   = warp & 3;
    const int wn   = warp >> 2;
    const int grp  = lane >> 2;
    const int tig  = lane & 3;
    const int row0 = blockIdx.y * GBM;   // row blocks on y (x iterates fastest)
    const int col0 = blockIdx.x * GBN;   // 2 column blocks adjacent in schedule

    const int arow = lane & 15;
    const int acolofs = (lane >> 4) * 8;
    const int brow = (lane & 7) + ((lane >> 4) << 3);
    const int bcolofs = ((lane >> 3) & 1) * 8;

    const int lrow = t >> 3;            // 0..31 base row (x4 via r)
    const int lkq  = (t & 7) * 4;       // 0..28

    float acc[2][8][4];
#pragma unroll
    for (int i = 0; i < 2; i++)
#pragma unroll
        for (int j = 0; j < 8; j++)
#pragma unroll
            for (int c = 0; c < 4; c++) acc[i][j][c] = 0.0f;

    // ---- prefetch A tile for kt=0 ----
    float4 va[4];
#pragma unroll
    for (int r = 0; r < 4; r++) {
        int row = lrow + r * 32;
        va[r] = make_float4(0.f, 0.f, 0.f, 0.f);
        if (row0 + row < N_NODES)
            va[r] = *(const float4*)&Am[(size_t)(row0 + row) * HDIM + lkq];
    }

    for (int kt = 0; kt < 512; kt += GBK) {
        const float* Wsrc = (kt < 256) ? Wl : Wr;
        const int kl = kt & 255;

        // 1) issue B loads (L2-hot weights), latency hidden by A split below
        float4 vb[4];
#pragma unroll
        for (int r = 0; r < 4; r++) {
            int row = lrow + r * 32;
            vb[r] = *(const float4*)&Wsrc[(size_t)(col0 + row) * HDIM + kl + lkq];
        }
        // 2) split + store A (consumes va)
#pragma unroll
        for (int r = 0; r < 4; r++)
            split_store(As_h, As_l, lrow + r * 32, lkq, va[r]);
        // 3) split + store B
#pragma unroll
        for (int r = 0; r < 4; r++)
            split_store(Bs_h, Bs_l, lrow + r * 32, lkq, vb[r]);
        __syncthreads();

        // 4) prefetch next A tile — LDG latency overlaps the MMA section
        if (kt + GBK < 512) {
            const float* Asrc = (kt + GBK < 256) ? Am : Ah;
            const int kl2 = (kt + GBK) & 255;
#pragma unroll
            for (int r = 0; r < 4; r++) {
                int row = lrow + r * 32;
                va[r] = make_float4(0.f, 0.f, 0.f, 0.f);
                if (row0 + row < N_NODES)
                    va[r] = *(const float4*)&Asrc[(size_t)(row0 + row) * HDIM + kl2 + lkq];
            }
        }

        // 5) MMA section
#pragma unroll
        for (int ks = 0; ks < 2; ks++) {
            const int k0 = ks * 16;
            uint32_t ah[2][4], al[2][4];
#pragma unroll
            for (int i = 0; i < 2; i++) {
                int m = wm * 32 + i * 16;
                ldmx4(ah[i], &As_h[m + arow][k0 + acolofs]);
                ldmx4(al[i], &As_l[m + arow][k0 + acolofs]);
            }
#pragma unroll
            for (int jp = 0; jp < 4; jp++) {
                int n = wn * 64 + jp * 16;
                uint32_t bh[4], bl[4];
                ldmx4(bh, &Bs_h[n + brow][k0 + bcolofs]);
                ldmx4(bl, &Bs_l[n + brow][k0 + bcolofs]);
#pragma unroll
                for (int i = 0; i < 2; i++) {
                    mma16816(acc[i][2 * jp],     ah[i], bh[0], bh[1]);
                    mma16816(acc[i][2 * jp],     ah[i], bl[0], bl[1]);
                    mma16816(acc[i][2 * jp],     al[i], bh[0], bh[1]);
                    mma16816(acc[i][2 * jp + 1], ah[i], bh[2], bh[3]);
                    mma16816(acc[i][2 * jp + 1], ah[i], bl[2], bl[3]);
                    mma16816(acc[i][2 * jp + 1], al[i], bh[2], bh[3]);
                }
            }
        }
        __syncthreads();
    }

    // ---- epilogue: bias + optional relu ----
#pragma unroll
    for (int i = 0; i < 2; i++) {
#pragma unroll
        for (int j = 0; j < 8; j++) {
            int col = col0 + wn * 64 + j * 8 + tig * 2;
            float b0 = bias[col], b1 = bias[col + 1];
            int r0 = row0 + wm * 32 + i * 16 + grp;
            int r1 = r0 + 8;
            float v0 = acc[i][j][0] + b0, v1 = acc[i][j][1] + b1;
            float v2 = acc[i][j][2] + b0, v3 = acc[i][j][3] + b1;
            if (do_relu) {
                v0 = fmaxf(v0, 0.f); v1 = fmaxf(v1, 0.f);
                v2 = fmaxf(v2, 0.f); v3 = fmaxf(v3, 0.f);
            }
            if (r0 < N_NODES) { float2 p; p.x = v0; p.y = v1;
                *(float2*)&C[(size_t)r0 * HDIM + col] = p; }
            if (r1 < N_NODES) { float2 p; p.x = v2; p.y = v3;
                *(float2*)&C[(size_t)r1 * HDIM + col] = p; }
        }
    }
}

// ---------------- launch ----------------------------------------------------
extern "C" void kernel_launch(void* const* d_in, const int* in_sizes, int n_in,
                              void* d_out, int out_size) {
    const float* x    = (const float*)d_in[0];
    const void*  ei   = d_in[1];
    const float* Wl   = (const float*)d_in[2];
    const float* Wr   = (const float*)d_in[3];
    const float* bias = (const float*)d_in[4];
    float*       out  = (float*)d_out;

    void *pA, *pB, *pM;
    cudaGetSymbolAddress(&pA, d_bufA);
    cudaGetSymbolAddress(&pB, d_bufB);
    cudaGetSymbolAddress(&pM, d_mean);
    float* bufA = (float*)pA;
    float* bufB = (float*)pB;
    float* mean = (float*)pM;

    int nblocks = (N_NODES + 255) / 256;
    zero_detect_kernel<<<nblocks, 256>>>(ei);

    int e2blocks = (E_EDGES / 2 + 255) / 256;
    hist_kernel<<<e2blocks, 256>>>(ei);
    scan_pass1<<<NBLK, SCAN_B>>>();
    scan_pass2<<<1, 128>>>();
    scan_pass3<<<NBLK, SCAN_B>>>();
    scatter_kernel<<<e2blocks, 256>>>(ei);

    dim3 ggrid(HDIM / GBN, (N_NODES + GBM - 1) / GBM);   // (2, 782): col pairs adjacent

    const float* hin = x;
    for (int l = 0; l < LAYERS; l++) {
        agg_kernel<<<N_NODES, 256>>>(hin);
        float* hout = (l == LAYERS - 1) ? out : ((l & 1) ? bufB : bufA);
        gemm_kernel<<<ggrid, 256>>>(mean, hin,
                                    Wl + (size_t)l * HDIM * HDIM,
                                    Wr + (size_t)l * HDIM * HDIM,
                                    bias + (size_t)l * HDIM,
                                    hout, (l < LAYERS - 1) ? 1 : 0);
        hin = hout;
    }
}

// round 16
// speedup vs baseline: 1.1273x; 1.0139x over previous
#include <cuda_runtime.h>
#include <cuda_bf16.h>
#include <cstdint>

#define N_NODES 100000
#define HDIM    256
#define E_EDGES 3200000
#define LAYERS  4
#define SCAN_B  1024
#define NBLK    ((N_NODES + SCAN_B - 1) / SCAN_B)   // 98

// ---------------- scratch (device globals; no allocation allowed) ----------
__device__ int   d_is64;
__device__ int   d_cnt[N_NODES];
__device__ int   d_off[N_NODES + 1];
__device__ int   d_cur[N_NODES];
__device__ int   d_src_sorted[E_EDGES];
__device__ int   d_bsum[128];
__device__ float d_mean[(size_t)N_NODES * HDIM];
__device__ float d_bufA[(size_t)N_NODES * HDIM];
__device__ float d_bufB[(size_t)N_NODES * HDIM];

// ---------------- dtype detection + CSR construction -----------------------
__device__ __forceinline__ int load_idx(const void* ei, long long pos) {
    if (d_is64) return (int)((const long long*)ei)[pos];
    return ((const int*)ei)[pos];
}

__global__ void zero_detect_kernel(const void* __restrict__ ei) {
    int i = blockIdx.x * blockDim.x + threadIdx.x;
    if (i < N_NODES) d_cnt[i] = 0;
    if (blockIdx.x == 0 && threadIdx.x == 0) {
        const long long* p = (const long long*)ei;
        int ok64 = 1;
        for (int q = 0; q < 64; q++) {
            long long v = p[q];
            if (v < 0 || v >= N_NODES) { ok64 = 0; break; }
        }
        d_is64 = ok64;
    }
}

__global__ void hist_kernel(const void* __restrict__ ei) {
    int e = blockIdx.x * blockDim.x + threadIdx.x;
    if (e < E_EDGES) {
        int d = load_idx(ei, (long long)E_EDGES + e);
        atomicAdd(&d_cnt[d], 1);
    }
}

__global__ void scan_pass1() {
    __shared__ int sm[SCAN_B];
    int tid = threadIdx.x;
    int gid = blockIdx.x * SCAN_B + tid;
    int v = (gid < N_NODES) ? d_cnt[gid] : 0;
    sm[tid] = v;
    __syncthreads();
    for (int ofs = 1; ofs < SCAN_B; ofs <<= 1) {
        int t = (tid >= ofs) ? sm[tid - ofs] : 0;
        __syncthreads();
        sm[tid] += t;
        __syncthreads();
    }
    if (gid < N_NODES) d_off[gid] = sm[tid] - v;
    if (tid == SCAN_B - 1) d_bsum[blockIdx.x] = sm[tid];
}

__global__ void scan_pass2() {
    __shared__ int sm[128];
    int tid = threadIdx.x;
    int v = (tid < NBLK) ? d_bsum[tid] : 0;
    sm[tid] = v;
    __syncthreads();
    for (int ofs = 1; ofs < 128; ofs <<= 1) {
        int t = (tid >= ofs) ? sm[tid - ofs] : 0;
        __syncthreads();
        sm[tid] += t;
        __syncthreads();
    }
    if (tid < NBLK) d_bsum[tid] = sm[tid] - v;
}

__global__ void scan_pass3() {
    int gid = blockIdx.x * SCAN_B + threadIdx.x;
    if (gid < N_NODES) {
        int o = d_off[gid] + d_bsum[blockIdx.x];
        d_off[gid] = o;
        d_cur[gid] = o;
    }
    if (gid == 0) d_off[N_NODES] = E_EDGES;
}

__global__ void scatter_kernel(const void* __restrict__ ei) {
    int e = blockIdx.x * blockDim.x + threadIdx.x;
    if (e < E_EDGES) {
        int s = load_idx(ei, e);
        int d = load_idx(ei, (long long)E_EDGES + e);
        int pos = atomicAdd(&d_cur[d], 1);
        d_src_sorted[pos] = s;
    }
}

// ---------------- mean aggregation: float4 gathers, unroll-8 MLP ------------
// Block = one node. 256 threads = 4 edge-slots x 64 channel-quads.
// Unroll-8 per slot (stride 32): 8 outstanding float4s per thread covers the
// modal degree (~32) in a single iteration.
__global__ __launch_bounds__(256) void agg_kernel(const float* __restrict__ hin) {
    __shared__ float4 red[256];
    const int i    = blockIdx.x;
    const int tid  = threadIdx.x;
    const int esub = tid >> 6;     // 0..3  edge slot
    const int c4   = tid & 63;     // 0..63 channel quad

    const int start = d_off[i];
    const int deg   = d_off[i + 1] - start;
    const int* __restrict__ idxp = d_src_sorted + start;

    float4 acc = make_float4(0.f, 0.f, 0.f, 0.f);
    int jj = esub;
    for (; jj + 28 < deg; jj += 32) {
        int s0 = idxp[jj],      s1 = idxp[jj + 4],  s2 = idxp[jj + 8],  s3 = idxp[jj + 12];
        int s4 = idxp[jj + 16], s5 = idxp[jj + 20], s6 = idxp[jj + 24], s7 = idxp[jj + 28];
        float4 v0 = *(const float4*)&hin[(size_t)s0 * HDIM + c4 * 4];
        float4 v1 = *(const float4*)&hin[(size_t)s1 * HDIM + c4 * 4];
        float4 v2 = *(const float4*)&hin[(size_t)s2 * HDIM + c4 * 4];
        float4 v3 = *(const float4*)&hin[(size_t)s3 * HDIM + c4 * 4];
        float4 v4 = *(const float4*)&hin[(size_t)s4 * HDIM + c4 * 4];
        float4 v5 = *(const float4*)&hin[(size_t)s5 * HDIM + c4 * 4];
        float4 v6 = *(const float4*)&hin[(size_t)s6 * HDIM + c4 * 4];
        float4 v7 = *(const float4*)&hin[(size_t)s7 * HDIM + c4 * 4];
        acc.x += v0.x; acc.y += v0.y; acc.z += v0.z; acc.w += v0.w;
        acc.x += v1.x; acc.y += v1.y; acc.z += v1.z; acc.w += v1.w;
        acc.x += v2.x; acc.y += v2.y; acc.z += v2.z; acc.w += v2.w;
        acc.x += v3.x; acc.y += v3.y; acc.z += v3.z; acc.w += v3.w;
        acc.x += v4.x; acc.y += v4.y; acc.z += v4.z; acc.w += v4.w;
        acc.x += v5.x; acc.y += v5.y; acc.z += v5.z; acc.w += v5.w;
        acc.x += v6.x; acc.y += v6.y; acc.z += v6.z; acc.w += v6.w;
        acc.x += v7.x; acc.y += v7.y; acc.z += v7.z; acc.w += v7.w;
    }
    for (; jj < deg; jj += 4) {
        float4 v = *(const float4*)&hin[(size_t)idxp[jj] * HDIM + c4 * 4];
        acc.x += v.x; acc.y += v.y; acc.z += v.z; acc.w += v.w;
    }

    red[tid] = acc;
    __syncthreads();
    if (tid < 64) {
        float4 a = red[tid], b = red[tid + 64], c = red[tid + 128], d = red[tid + 192];
        float inv = 1.0f / (float)max(deg, 1);
        float4 o;
        o.x = (a.x + b.x + c.x + d.x) * inv;
        o.y = (a.y + b.y + c.y + d.y) * inv;
        o.z = (a.z + b.z + c.z + d.z) * inv;
        o.w = (a.w + b.w + c.w + d.w) * inv;
        *(float4*)&d_mean[(size_t)i * HDIM + tid * 4] = o;
    }
}

// ---------------- tensor-core GEMM: C = mean@Wl^T + h@Wr^T + b (+ReLU) -----
// Split-bf16 hi/lo 3-product fp32 emulation, ldmatrix.x4 fragments,
// register-prefetched A tiles. (R12 configuration — local optimum.)
#define GBM  128
#define GBN  128
#define GBK  32
#define GSTR 40

__device__ __forceinline__ void mma16816(float c[4], const uint32_t a[4],
                                         uint32_t b0, uint32_t b1) {
    asm volatile(
        "mma.sync.aligned.m16n8k16.row.col.f32.bf16.bf16.f32 "
        "{%0,%1,%2,%3}, {%4,%5,%6,%7}, {%8,%9}, {%0,%1,%2,%3};"
        : "+f"(c[0]), "+f"(c[1]), "+f"(c[2]), "+f"(c[3])
        : "r"(a[0]), "r"(a[1]), "r"(a[2]), "r"(a[3]), "r"(b0), "r"(b1));
}

__device__ __forceinline__ void ldmx4(uint32_t r[4], const void* p) {
    uint32_t a = (uint32_t)__cvta_generic_to_shared(p);
    asm volatile("ldmatrix.sync.aligned.m8n8.x4.shared.b16 {%0,%1,%2,%3}, [%4];"
                 : "=r"(r[0]), "=r"(r[1]), "=r"(r[2]), "=r"(r[3]) : "r"(a));
}

__device__ __forceinline__ uint32_t pack_bf2(__nv_bfloat16 a, __nv_bfloat16 b) {
    uint16_t ua = *(uint16_t*)&a, ub = *(uint16_t*)&b;
    return (uint32_t)ua | ((uint32_t)ub << 16);
}

__device__ __forceinline__ void split_store(
    __nv_bfloat16 (*Sh)[GSTR], __nv_bfloat16 (*Sl)[GSTR],
    int row, int kq, float4 v)
{
    __nv_bfloat16 h0 = __float2bfloat16_rn(v.x);
    __nv_bfloat16 h1 = __float2bfloat16_rn(v.y);
    __nv_bfloat16 h2 = __float2bfloat16_rn(v.z);
    __nv_bfloat16 h3 = __float2bfloat16_rn(v.w);
    __nv_bfloat16 l0 = __float2bfloat16_rn(v.x - __bfloat162float(h0));
    __nv_bfloat16 l1 = __float2bfloat16_rn(v.y - __bfloat162float(h1));
    __nv_bfloat16 l2 = __float2bfloat16_rn(v.z - __bfloat162float(h2));
    __nv_bfloat16 l3 = __float2bfloat16_rn(v.w - __bfloat162float(h3));
    *(uint32_t*)&Sh[row][kq]     = pack_bf2(h0, h1);
    *(uint32_t*)&Sh[row][kq + 2] = pack_bf2(h2, h3);
    *(uint32_t*)&Sl[row][kq]     = pack_bf2(l0, l1);
    *(uint32_t*)&Sl[row][kq + 2] = pack_bf2(l2, l3);
}

__global__ __launch_bounds__(256, 2) void gemm_kernel(
    const float* __restrict__ Am,   // mean  [N_NODES, 256]
    const float* __restrict__ Ah,   // h_in  [N_NODES, 256]
    const float* __restrict__ Wl,   // [256, 256] row-major (o, k)
    const float* __restrict__ Wr,   // [256, 256]
    const float* __restrict__ bias, // [256]
    float* __restrict__ C,          // [N_NODES, 256]
    int do_relu)
{
    __shared__ __nv_bfloat16 As_h[GBM][GSTR];
    __shared__ __nv_bfloat16 As_l[GBM][GSTR];
    __shared__ __nv_bfloat16 Bs_h[GBN][GSTR];
    __shared__ __nv_bfloat16 Bs_l[GBN][GSTR];

    const int t    = threadIdx.x;
    const int warp = t >> 5;
    const int lane = t & 31;
    const int wm   = warp & 3;
    const int wn   = warp >> 2;
    const int grp  = lane >> 2;
    const int tig  = lane & 3;
    const int row0 = blockIdx.y * GBM;   // row blocks on y (x iterates fastest)
    const int col0 = blockIdx.x * GBN;   // 2 column blocks adjacent in schedule

    const int arow = lane & 15;
    const int acolofs = (lane >> 4) * 8;
    const int brow = (lane & 7) + ((lane >> 4) << 3);
    const int bcolofs = ((lane >> 3) & 1) * 8;

    const int lrow = t >> 3;            // 0..31 base row (x4 via r)
    const int lkq  = (t & 7) * 4;       // 0..28

    float acc[2][8][4];
#pragma unroll
    for (int i = 0; i < 2; i++)
#pragma unroll
        for (int j = 0; j < 8; j++)
#pragma unroll
            for (int c = 0; c < 4; c++) acc[i][j][c] = 0.0f;

    // ---- prefetch A tile for kt=0 ----
    float4 va[4];
#pragma unroll
    for (int r = 0; r < 4; r++) {
        int row = lrow + r * 32;
        va[r] = make_float4(0.f, 0.f, 0.f, 0.f);
        if (row0 + row < N_NODES)
            va[r] = *(const float4*)&Am[(size_t)(row0 + row) * HDIM + lkq];
    }

    for (int kt = 0; kt < 512; kt += GBK) {
        const float* Wsrc = (kt < 256) ? Wl : Wr;
        const int kl = kt & 255;

        // 1) issue B loads (L2-hot weights), latency hidden by A split below
        float4 vb[4];
#pragma unroll
        for (int r = 0; r < 4; r++) {
            int row = lrow + r * 32;
            vb[r] = *(const float4*)&Wsrc[(size_t)(col0 + row) * HDIM + kl + lkq];
        }
        // 2) split + store A (consumes va)
#pragma unroll
        for (int r = 0; r < 4; r++)
            split_store(As_h, As_l, lrow + r * 32, lkq, va[r]);
        // 3) split + store B
#pragma unroll
        for (int r = 0; r < 4; r++)
            split_store(Bs_h, Bs_l, lrow + r * 32, lkq, vb[r]);
        __syncthreads();

        // 4) prefetch next A tile — LDG latency overlaps the MMA section
        if (kt + GBK < 512) {
            const float* Asrc = (kt + GBK < 256) ? Am : Ah;
            const int kl2 = (kt + GBK) & 255;
#pragma unroll
            for (int r = 0; r < 4; r++) {
                int row = lrow + r * 32;
                va[r] = make_float4(0.f, 0.f, 0.f, 0.f);
                if (row0 + row < N_NODES)
                    va[r] = *(const float4*)&Asrc[(size_t)(row0 + row) * HDIM + kl2 + lkq];
            }
        }

        // 5) MMA section
#pragma unroll
        for (int ks = 0; ks < 2; ks++) {
            const int k0 = ks * 16;
            uint32_t ah[2][4], al[2][4];
#pragma unroll
            for (int i = 0; i < 2; i++) {
                int m = wm * 32 + i * 16;
                ldmx4(ah[i], &As_h[m + arow][k0 + acolofs]);
                ldmx4(al[i], &As_l[m + arow][k0 + acolofs]);
            }
#pragma unroll
            for (int jp = 0; jp < 4; jp++) {
                int n = wn * 64 + jp * 16;
                uint32_t bh[4], bl[4];
                ldmx4(bh, &Bs_h[n + brow][k0 + bcolofs]);
                ldmx4(bl, &Bs_l[n + brow][k0 + bcolofs]);
#pragma unroll
                for (int i = 0; i < 2; i++) {
                    mma16816(acc[i][2 * jp],     ah[i], bh[0], bh[1]);
                    mma16816(acc[i][2 * jp],     ah[i], bl[0], bl[1]);
                    mma16816(acc[i][2 * jp],     al[i], bh[0], bh[1]);
                    mma16816(acc[i][2 * jp + 1], ah[i], bh[2], bh[3]);
                    mma16816(acc[i][2 * jp + 1], ah[i], bl[2], bl[3]);
                    mma16816(acc[i][2 * jp + 1], al[i], bh[2], bh[3]);
                }
            }
        }
        __syncthreads();
    }

    // ---- epilogue: bias + optional relu ----
#pragma unroll
    for (int i = 0; i < 2; i++) {
#pragma unroll
        for (int j = 0; j < 8; j++) {
            int col = col0 + wn * 64 + j * 8 + tig * 2;
            float b0 = bias[col], b1 = bias[col + 1];
            int r0 = row0 + wm * 32 + i * 16 + grp;
            int r1 = r0 + 8;
            float v0 = acc[i][j][0] + b0, v1 = acc[i][j][1] + b1;
            float v2 = acc[i][j][2] + b0, v3 = acc[i][j][3] + b1;
            if (do_relu) {
                v0 = fmaxf(v0, 0.f); v1 = fmaxf(v1, 0.f);
                v2 = fmaxf(v2, 0.f); v3 = fmaxf(v3, 0.f);
            }
            if (r0 < N_NODES) { float2 p; p.x = v0; p.y = v1;
                *(float2*)&C[(size_t)r0 * HDIM + col] = p; }
            if (r1 < N_NODES) { float2 p; p.x = v2; p.y = v3;
                *(float2*)&C[(size_t)r1 * HDIM + col] = p; }
        }
    }
}

// ---------------- launch ----------------------------------------------------
extern "C" void kernel_launch(void* const* d_in, const int* in_sizes, int n_in,
                              void* d_out, int out_size) {
    const float* x    = (const float*)d_in[0];
    const void*  ei   = d_in[1];
    const float* Wl   = (const float*)d_in[2];
    const float* Wr   = (const float*)d_in[3];
    const float* bias = (const float*)d_in[4];
    float*       out  = (float*)d_out;

    void *pA, *pB, *pM;
    cudaGetSymbolAddress(&pA, d_bufA);
    cudaGetSymbolAddress(&pB, d_bufB);
    cudaGetSymbolAddress(&pM, d_mean);
    float* bufA = (float*)pA;
    float* bufB = (float*)pB;
    float* mean = (float*)pM;

    int nblocks = (N_NODES + 255) / 256;
    zero_detect_kernel<<<nblocks, 256>>>(ei);

    int eblocks = (E_EDGES + 255) / 256;
    hist_kernel<<<eblocks, 256>>>(ei);
    scan_pass1<<<NBLK, SCAN_B>>>();
    scan_pass2<<<1, 128>>>();
    scan_pass3<<<NBLK, SCAN_B>>>();
    scatter_kernel<<<eblocks, 256>>>(ei);

    dim3 ggrid(HDIM / GBN, (N_NODES + GBM - 1) / GBM);   // (2, 782): col pairs adjacent

    const float* hin = x;
    for (int l = 0; l < LAYERS; l++) {
        agg_kernel<<<N_NODES, 256>>>(hin);
        float* hout = (l == LAYERS - 1) ? out : ((l & 1) ? bufB : bufA);
        gemm_kernel<<<ggrid, 256>>>(mean, hin,
                                    Wl + (size_t)l * HDIM * HDIM,
                                    Wr + (size_t)l * HDIM * HDIM,
                                    bias + (size_t)l * HDIM,
                                    hout, (l < LAYERS - 1) ? 1 : 0);
        hin = hout;
    }
}

// round 17
// speedup vs baseline: 1.1406x; 1.0118x over previous
#include <cuda_runtime.h>
#include <cuda_bf16.h>
#include <cstdint>

#define N_NODES 100000
#define HDIM    256
#define E_EDGES 3200000
#define LAYERS  4
#define SCAN_B  1024
#define NBLK    ((N_NODES + SCAN_B - 1) / SCAN_B)   // 98
#define AGG_GRID 1184                               // 8 blocks/SM persistent

// ---------------- scratch (device globals; no allocation allowed) ----------
__device__ int   d_is64;
__device__ int   d_cnt[N_NODES];
__device__ int   d_off[N_NODES + 1];
__device__ int   d_cur[N_NODES];
__device__ int   d_src_sorted[E_EDGES];
__device__ int   d_bsum[128];
__device__ float d_mean[(size_t)N_NODES * HDIM];
__device__ float d_bufA[(size_t)N_NODES * HDIM];
__device__ float d_bufB[(size_t)N_NODES * HDIM];

// ---------------- dtype detection + CSR construction -----------------------
__device__ __forceinline__ int load_idx(const void* ei, long long pos) {
    if (d_is64) return (int)((const long long*)ei)[pos];
    return ((const int*)ei)[pos];
}

__global__ void zero_detect_kernel(const void* __restrict__ ei) {
    int i = blockIdx.x * blockDim.x + threadIdx.x;
    if (i < N_NODES) d_cnt[i] = 0;
    if (blockIdx.x == 0 && threadIdx.x == 0) {
        const long long* p = (const long long*)ei;
        int ok64 = 1;
        for (int q = 0; q < 64; q++) {
            long long v = p[q];
            if (v < 0 || v >= N_NODES) { ok64 = 0; break; }
        }
        d_is64 = ok64;
    }
}

__global__ void hist_kernel(const void* __restrict__ ei) {
    int e = blockIdx.x * blockDim.x + threadIdx.x;
    if (e < E_EDGES) {
        int d = load_idx(ei, (long long)E_EDGES + e);
        atomicAdd(&d_cnt[d], 1);
    }
}

__global__ void scan_pass1() {
    __shared__ int sm[SCAN_B];
    int tid = threadIdx.x;
    int gid = blockIdx.x * SCAN_B + tid;
    int v = (gid < N_NODES) ? d_cnt[gid] : 0;
    sm[tid] = v;
    __syncthreads();
    for (int ofs = 1; ofs < SCAN_B; ofs <<= 1) {
        int t = (tid >= ofs) ? sm[tid - ofs] : 0;
        __syncthreads();
        sm[tid] += t;
        __syncthreads();
    }
    if (gid < N_NODES) d_off[gid] = sm[tid] - v;
    if (tid == SCAN_B - 1) d_bsum[blockIdx.x] = sm[tid];
}

__global__ void scan_pass2() {
    __shared__ int sm[128];
    int tid = threadIdx.x;
    int v = (tid < NBLK) ? d_bsum[tid] : 0;
    sm[tid] = v;
    __syncthreads();
    for (int ofs = 1; ofs < 128; ofs <<= 1) {
        int t = (tid >= ofs) ? sm[tid - ofs] : 0;
        __syncthreads();
        sm[tid] += t;
        __syncthreads();
    }
    if (tid < NBLK) d_bsum[tid] = sm[tid] - v;
}

__global__ void scan_pass3() {
    int gid = blockIdx.x * SCAN_B + threadIdx.x;
    if (gid < N_NODES) {
        int o = d_off[gid] + d_bsum[blockIdx.x];
        d_off[gid] = o;
        d_cur[gid] = o;
    }
    if (gid == 0) d_off[N_NODES] = E_EDGES;
}

__global__ void scatter_kernel(const void* __restrict__ ei) {
    int e = blockIdx.x * blockDim.x + threadIdx.x;
    if (e < E_EDGES) {
        int s = load_idx(ei, e);
        int d = load_idx(ei, (long long)E_EDGES + e);
        int pos = atomicAdd(&d_cur[d], 1);
        d_src_sorted[pos] = s;
    }
}

// ---------------- mean aggregation: persistent grid, float4 unroll-8 --------
// 1184 persistent blocks (8/SM); each loops over nodes with grid stride.
// 256 threads = 4 edge-slots x 64 channel-quads; unroll-8 per slot.
__global__ __launch_bounds__(256) void agg_kernel(const float* __restrict__ hin) {
    __shared__ float4 red[256];
    const int tid  = threadIdx.x;
    const int esub = tid >> 6;     // 0..3  edge slot
    const int c4   = tid & 63;     // 0..63 channel quad

    for (int i = blockIdx.x; i < N_NODES; i += AGG_GRID) {
        const int start = d_off[i];
        const int deg   = d_off[i + 1] - start;
        const int* __restrict__ idxp = d_src_sorted + start;

        float4 acc = make_float4(0.f, 0.f, 0.f, 0.f);
        int jj = esub;
        for (; jj + 28 < deg; jj += 32) {
            int s0 = idxp[jj],      s1 = idxp[jj + 4],  s2 = idxp[jj + 8],  s3 = idxp[jj + 12];
            int s4 = idxp[jj + 16], s5 = idxp[jj + 20], s6 = idxp[jj + 24], s7 = idxp[jj + 28];
            float4 v0 = *(const float4*)&hin[(size_t)s0 * HDIM + c4 * 4];
            float4 v1 = *(const float4*)&hin[(size_t)s1 * HDIM + c4 * 4];
            float4 v2 = *(const float4*)&hin[(size_t)s2 * HDIM + c4 * 4];
            float4 v3 = *(const float4*)&hin[(size_t)s3 * HDIM + c4 * 4];
            float4 v4 = *(const float4*)&hin[(size_t)s4 * HDIM + c4 * 4];
            float4 v5 = *(const float4*)&hin[(size_t)s5 * HDIM + c4 * 4];
            float4 v6 = *(const float4*)&hin[(size_t)s6 * HDIM + c4 * 4];
            float4 v7 = *(const float4*)&hin[(size_t)s7 * HDIM + c4 * 4];
            acc.x += v0.x; acc.y += v0.y; acc.z += v0.z; acc.w += v0.w;
            acc.x += v1.x; acc.y += v1.y; acc.z += v1.z; acc.w += v1.w;
            acc.x += v2.x; acc.y += v2.y; acc.z += v2.z; acc.w += v2.w;
            acc.x += v3.x; acc.y += v3.y; acc.z += v3.z; acc.w += v3.w;
            acc.x += v4.x; acc.y += v4.y; acc.z += v4.z; acc.w += v4.w;
            acc.x += v5.x; acc.y += v5.y; acc.z += v5.z; acc.w += v5.w;
            acc.x += v6.x; acc.y += v6.y; acc.z += v6.z; acc.w += v6.w;
            acc.x += v7.x; acc.y += v7.y; acc.z += v7.z; acc.w += v7.w;
        }
        for (; jj < deg; jj += 4) {
            float4 v = *(const float4*)&hin[(size_t)idxp[jj] * HDIM + c4 * 4];
            acc.x += v.x; acc.y += v.y; acc.z += v.z; acc.w += v.w;
        }

        red[tid] = acc;
        __syncthreads();
        if (tid < 64) {
            float4 a = red[tid], b = red[tid + 64], c = red[tid + 128], d = red[tid + 192];
            float inv = 1.0f / (float)max(deg, 1);
            float4 o;
            o.x = (a.x + b.x + c.x + d.x) * inv;
            o.y = (a.y + b.y + c.y + d.y) * inv;
            o.z = (a.z + b.z + c.z + d.z) * inv;
            o.w = (a.w + b.w + c.w + d.w) * inv;
            *(float4*)&d_mean[(size_t)i * HDIM + tid * 4] = o;
        }
        __syncthreads();   // guard red[] reuse across node iterations
    }
}

// ---------------- tensor-core GEMM: C = mean@Wl^T + h@Wr^T + b (+ReLU) -----
// Split-bf16 hi/lo 3-product fp32 emulation, ldmatrix.x4 fragments,
// register-prefetched A tiles. (R12 configuration — local optimum.)
#define GBM  128
#define GBN  128
#define GBK  32
#define GSTR 40

__device__ __forceinline__ void mma16816(float c[4], const uint32_t a[4],
                                         uint32_t b0, uint32_t b1) {
    asm volatile(
        "mma.sync.aligned.m16n8k16.row.col.f32.bf16.bf16.f32 "
        "{%0,%1,%2,%3}, {%4,%5,%6,%7}, {%8,%9}, {%0,%1,%2,%3};"
        : "+f"(c[0]), "+f"(c[1]), "+f"(c[2]), "+f"(c[3])
        : "r"(a[0]), "r"(a[1]), "r"(a[2]), "r"(a[3]), "r"(b0), "r"(b1));
}

__device__ __forceinline__ void ldmx4(uint32_t r[4], const void* p) {
    uint32_t a = (uint32_t)__cvta_generic_to_shared(p);
    asm volatile("ldmatrix.sync.aligned.m8n8.x4.shared.b16 {%0,%1,%2,%3}, [%4];"
                 : "=r"(r[0]), "=r"(r[1]), "=r"(r[2]), "=r"(r[3]) : "r"(a));
}

__device__ __forceinline__ uint32_t pack_bf2(__nv_bfloat16 a, __nv_bfloat16 b) {
    uint16_t ua = *(uint16_t*)&a, ub = *(uint16_t*)&b;
    return (uint32_t)ua | ((uint32_t)ub << 16);
}

__device__ __forceinline__ void split_store(
    __nv_bfloat16 (*Sh)[GSTR], __nv_bfloat16 (*Sl)[GSTR],
    int row, int kq, float4 v)
{
    __nv_bfloat16 h0 = __float2bfloat16_rn(v.x);
    __nv_bfloat16 h1 = __float2bfloat16_rn(v.y);
    __nv_bfloat16 h2 = __float2bfloat16_rn(v.z);
    __nv_bfloat16 h3 = __float2bfloat16_rn(v.w);
    __nv_bfloat16 l0 = __float2bfloat16_rn(v.x - __bfloat162float(h0));
    __nv_bfloat16 l1 = __float2bfloat16_rn(v.y - __bfloat162float(h1));
    __nv_bfloat16 l2 = __float2bfloat16_rn(v.z - __bfloat162float(h2));
    __nv_bfloat16 l3 = __float2bfloat16_rn(v.w - __bfloat162float(h3));
    *(uint32_t*)&Sh[row][kq]     = pack_bf2(h0, h1);
    *(uint32_t*)&Sh[row][kq + 2] = pack_bf2(h2, h3);
    *(uint32_t*)&Sl[row][kq]     = pack_bf2(l0, l1);
    *(uint32_t*)&Sl[row][kq + 2] = pack_bf2(l2, l3);
}

__global__ __launch_bounds__(256, 2) void gemm_kernel(
    const float* __restrict__ Am,   // mean  [N_NODES, 256]
    const float* __restrict__ Ah,   // h_in  [N_NODES, 256]
    const float* __restrict__ Wl,   // [256, 256] row-major (o, k)
    const float* __restrict__ Wr,   // [256, 256]
    const float* __restrict__ bias, // [256]
    float* __restrict__ C,          // [N_NODES, 256]
    int do_relu)
{
    __shared__ __nv_bfloat16 As_h[GBM][GSTR];
    __shared__ __nv_bfloat16 As_l[GBM][GSTR];
    __shared__ __nv_bfloat16 Bs_h[GBN][GSTR];
    __shared__ __nv_bfloat16 Bs_l[GBN][GSTR];

    const int t    = threadIdx.x;
    const int warp = t >> 5;
    const int lane = t & 31;
    const int wm   = warp & 3;
    const int wn   = warp >> 2;
    const int grp  = lane >> 2;
    const int tig  = lane & 3;
    const int row0 = blockIdx.y * GBM;   // row blocks on y (x iterates fastest)
    const int col0 = blockIdx.x * GBN;   // 2 column blocks adjacent in schedule

    const int arow = lane & 15;
    const int acolofs = (lane >> 4) * 8;
    const int brow = (lane & 7) + ((lane >> 4) << 3);
    const int bcolofs = ((lane >> 3) & 1) * 8;

    const int lrow = t >> 3;            // 0..31 base row (x4 via r)
    const int lkq  = (t & 7) * 4;       // 0..28

    float acc[2][8][4];
#pragma unroll
    for (int i = 0; i < 2; i++)
#pragma unroll
        for (int j = 0; j < 8; j++)
#pragma unroll
            for (int c = 0; c < 4; c++) acc[i][j][c] = 0.0f;

    // ---- prefetch A tile for kt=0 ----
    float4 va[4];
#pragma unroll
    for (int r = 0; r < 4; r++) {
        int row = lrow + r * 32;
        va[r] = make_float4(0.f, 0.f, 0.f, 0.f);
        if (row0 + row < N_NODES)
            va[r] = *(const float4*)&Am[(size_t)(row0 + row) * HDIM + lkq];
    }

    for (int kt = 0; kt < 512; kt += GBK) {
        const float* Wsrc = (kt < 256) ? Wl : Wr;
        const int kl = kt & 255;

        // 1) issue B loads (L2-hot weights), latency hidden by A split below
        float4 vb[4];
#pragma unroll
        for (int r = 0; r < 4; r++) {
            int row = lrow + r * 32;
            vb[r] = *(const float4*)&Wsrc[(size_t)(col0 + row) * HDIM + kl + lkq];
        }
        // 2) split + store A (consumes va)
#pragma unroll
        for (int r = 0; r < 4; r++)
            split_store(As_h, As_l, lrow + r * 32, lkq, va[r]);
        // 3) split + store B
#pragma unroll
        for (int r = 0; r < 4; r++)
            split_store(Bs_h, Bs_l, lrow + r * 32, lkq, vb[r]);
        __syncthreads();

        // 4) prefetch next A tile — LDG latency overlaps the MMA section
        if (kt + GBK < 512) {
            const float* Asrc = (kt + GBK < 256) ? Am : Ah;
            const int kl2 = (kt + GBK) & 255;
#pragma unroll
            for (int r = 0; r < 4; r++) {
                int row = lrow + r * 32;
                va[r] = make_float4(0.f, 0.f, 0.f, 0.f);
                if (row0 + row < N_NODES)
                    va[r] = *(const float4*)&Asrc[(size_t)(row0 + row) * HDIM + kl2 + lkq];
            }
        }

        // 5) MMA section
#pragma unroll
        for (int ks = 0; ks < 2; ks++) {
            const int k0 = ks * 16;
            uint32_t ah[2][4], al[2][4];
#pragma unroll
            for (int i = 0; i < 2; i++) {
                int m = wm * 32 + i * 16;
                ldmx4(ah[i], &As_h[m + arow][k0 + acolofs]);
                ldmx4(al[i], &As_l[m + arow][k0 + acolofs]);
            }
#pragma unroll
            for (int jp = 0; jp < 4; jp++) {
                int n = wn * 64 + jp * 16;
                uint32_t bh[4], bl[4];
                ldmx4(bh, &Bs_h[n + brow][k0 + bcolofs]);
                ldmx4(bl, &Bs_l[n + brow][k0 + bcolofs]);
#pragma unroll
                for (int i = 0; i < 2; i++) {
                    mma16816(acc[i][2 * jp],     ah[i], bh[0], bh[1]);
                    mma16816(acc[i][2 * jp],     ah[i], bl[0], bl[1]);
                    mma16816(acc[i][2 * jp],     al[i], bh[0], bh[1]);
                    mma16816(acc[i][2 * jp + 1], ah[i], bh[2], bh[3]);
                    mma16816(acc[i][2 * jp + 1], ah[i], bl[2], bl[3]);
                    mma16816(acc[i][2 * jp + 1], al[i], bh[2], bh[3]);
                }
            }
        }
        __syncthreads();
    }

    // ---- epilogue: bias + optional relu ----
#pragma unroll
    for (int i = 0; i < 2; i++) {
#pragma unroll
        for (int j = 0; j < 8; j++) {
            int col = col0 + wn * 64 + j * 8 + tig * 2;
            float b0 = bias[col], b1 = bias[col + 1];
            int r0 = row0 + wm * 32 + i * 16 + grp;
            int r1 = r0 + 8;
            float v0 = acc[i][j][0] + b0, v1 = acc[i][j][1] + b1;
            float v2 = acc[i][j][2] + b0, v3 = acc[i][j][3] + b1;
            if (do_relu) {
                v0 = fmaxf(v0, 0.f); v1 = fmaxf(v1, 0.f);
                v2 = fmaxf(v2, 0.f); v3 = fmaxf(v3, 0.f);
            }
            if (r0 < N_NODES) { float2 p; p.x = v0; p.y = v1;
                *(float2*)&C[(size_t)r0 * HDIM + col] = p; }
            if (r1 < N_NODES) { float2 p; p.x = v2; p.y = v3;
                *(float2*)&C[(size_t)r1 * HDIM + col] = p; }
        }
    }
}

// ---------------- launch ----------------------------------------------------
extern "C" void kernel_launch(void* const* d_in, const int* in_sizes, int n_in,
                              void* d_out, int out_size) {
    const float* x    = (const float*)d_in[0];
    const void*  ei   = d_in[1];
    const float* Wl   = (const float*)d_in[2];
    const float* Wr   = (const float*)d_in[3];
    const float* bias = (const float*)d_in[4];
    float*       out  = (float*)d_out;

    void *pA, *pB, *pM;
    cudaGetSymbolAddress(&pA, d_bufA);
    cudaGetSymbolAddress(&pB, d_bufB);
    cudaGetSymbolAddress(&pM, d_mean);
    float* bufA = (float*)pA;
    float* bufB = (float*)pB;
    float* mean = (float*)pM;

    int nblocks = (N_NODES + 255) / 256;
    zero_detect_kernel<<<nblocks, 256>>>(ei);

    int eblocks = (E_EDGES + 255) / 256;
    hist_kernel<<<eblocks, 256>>>(ei);
    scan_pass1<<<NBLK, SCAN_B>>>();
    scan_pass2<<<1, 128>>>();
    scan_pass3<<<NBLK, SCAN_B>>>();
    scatter_kernel<<<eblocks, 256>>>(ei);

    dim3 ggrid(HDIM / GBN, (N_NODES + GBM - 1) / GBM);   // (2, 782): col pairs adjacent

    const float* hin = x;
    for (int l = 0; l < LAYERS; l++) {
        agg_kernel<<<AGG_GRID, 256>>>(hin);
        float* hout = (l == LAYERS - 1) ? out : ((l & 1) ? bufB : bufA);
        gemm_kernel<<<ggrid, 256>>>(mean, hin,
                                    Wl + (size_t)l * HDIM * HDIM,
                                    Wr + (size_t)l * HDIM * HDIM,
                                    bias + (size_t)l * HDIM,
                                    hout, (l < LAYERS - 1) ? 1 : 0);
        hin = hout;
    }
}